// round 7
// baseline (speedup 1.0000x reference)
#include <cuda_runtime.h>
#include <cstdint>

// B=4096, T=1024, H=15
// Inputs: x[B*T], w_ih[15], w_hh[225], b_ih[15], b_hh[15], w_lin[15], b_lin[1]
// Output: out[B*T] float32
//
// Register-resident RNN: 8 lanes per batch; lane li owns hidden rows li and
// li+8 (lane 7's second row is the linear head, one step delayed). Hidden
// state stays in 2 registers/lane; the per-step broadcast is 15 shfl.sync
// (width=8) — zero shared memory, zero barriers in the main loop.

#define T_      1024
#define THREADS 64            // 2 warps = 8 groups (batches) per CTA
#define BPC     8
#define GRID    (4096 / BPC)  // 512 CTAs

__device__ __forceinline__ float tanha(float x) {
    float r; asm("tanh.approx.f32 %0, %1;" : "=f"(r) : "f"(x)); return r;
}

__global__ void __launch_bounds__(THREADS)
rnn_kernel(const float* __restrict__ x,
           const float* __restrict__ w_ih, const float* __restrict__ w_hh,
           const float* __restrict__ b_ih, const float* __restrict__ b_hh,
           const float* __restrict__ w_lin, const float* __restrict__ b_lin,
           float* __restrict__ out)
{
    const int tid  = threadIdx.x;
    const int lane = tid & 31;
    const int li   = lane & 7;               // lane within 8-lane group
    const int g    = tid >> 3;               // 0..7: batch within CTA
    const int batch = blockIdx.x * BPC + g;
    const bool is_head = (li == 7);

    // Rows: r0 = li (0..7), r1 = li + 8 (8..14; "15" = head for lane 7)
    float w0[15], w1[15], wih0, wih1, bias0, bias1;
#pragma unroll
    for (int j = 0; j < 15; j++) w0[j] = w_hh[li * 15 + j];
    wih0  = w_ih[li];
    bias0 = b_ih[li] + b_hh[li];
    if (!is_head) {
        const int r1 = li + 8;
#pragma unroll
        for (int j = 0; j < 15; j++) w1[j] = w_hh[r1 * 15 + j];
        wih1  = w_ih[r1];
        bias1 = b_ih[r1] + b_hh[r1];
    } else {
#pragma unroll
        for (int j = 0; j < 15; j++) w1[j] = w_lin[j];
        wih1  = 0.0f;
        bias1 = b_lin[0];
    }

    float hA = 0.0f, hB = 0.0f;              // h0 = 0
    const float* xrow = x   + (size_t)batch * T_;
    float*       orow = out + (size_t)batch * T_;

    float o0 = 0.f, o1 = 0.f, o2 = 0.f, o3 = 0.f;

    float4 xn = *reinterpret_cast<const float4*>(xrow);   // x[0..3]

#pragma unroll 1
    for (int m = 0; m < 256; ++m) {
        const float4 xc = xn;
        xn = *reinterpret_cast<const float4*>(xrow + (((m + 1) & 255) << 2));

#pragma unroll
        for (int u = 0; u < 4; ++u) {
            const float xv = (u == 0) ? xc.x : (u == 1) ? xc.y : (u == 2) ? xc.z : xc.w;

            // Gather h[0..14]: 15 independent width-8 shuffles
            float h[15];
#pragma unroll
            for (int j = 0; j < 8; ++j) h[j]     = __shfl_sync(0xffffffffu, hA, j, 8);
#pragma unroll
            for (int j = 0; j < 7; ++j) h[8 + j] = __shfl_sync(0xffffffffu, hB, j, 8);

            // Two 15-term dots (rows r0, r1), 3 accumulators each
            float p0 = fmaf(xv, wih0, bias0);
            float p1 = fmaf(xv, wih1, bias1);
            float a0 = fmaf(w0[0], h[0], p0);
            float a1 = w0[1] * h[1];
            float a2 = w0[2] * h[2];
            float c0 = fmaf(w1[0], h[0], p1);
            float c1 = w1[1] * h[1];
            float c2 = w1[2] * h[2];
#pragma unroll
            for (int j = 3; j < 15; j += 3) {
                a0 = fmaf(w0[j + 0], h[j + 0], a0);
                a1 = fmaf(w0[j + 1], h[j + 1], a1);
                a2 = fmaf(w0[j + 2], h[j + 2], a2);
                c0 = fmaf(w1[j + 0], h[j + 0], c0);
                c1 = fmaf(w1[j + 1], h[j + 1], c1);
                c2 = fmaf(w1[j + 2], h[j + 2], c2);
            }
            const float acc0 = a0 + (a1 + a2);
            const float acc1 = c0 + (c1 + c2);

            hA = tanha(acc0);
            const float tB = tanha(acc1);
            hB = is_head ? acc1 : tB;        // lane7 keeps raw head value (never gathered)

            // Head schedule: lane7's acc1 at step t=4m+u equals out[t-1]
            if (u == 0) {
                o3 = acc1;
                if (m > 0 && is_head)
                    *reinterpret_cast<float4*>(orow + ((m - 1) << 2)) =
                        make_float4(o0, o1, o2, o3);
            } else if (u == 1) { o0 = acc1; }
            else if (u == 2)   { o1 = acc1; }
            else               { o2 = acc1; }
        }
    }

    // Epilogue: out[1023] = head dot on final h; flush out[1020..1023]
    {
        float h[15];
#pragma unroll
        for (int j = 0; j < 8; ++j) h[j]     = __shfl_sync(0xffffffffu, hA, j, 8);
#pragma unroll
        for (int j = 0; j < 7; ++j) h[8 + j] = __shfl_sync(0xffffffffu, hB, j, 8);
        float c0 = bias1;      // lane7: w1 = w_lin, bias1 = b_lin
        float c1 = 0.0f;
        float c2 = 0.0f;
#pragma unroll
        for (int j = 0; j < 15; j += 3) {
            c0 = fmaf(w1[j + 0], h[j + 0], c0);
            c1 = fmaf(w1[j + 1], h[j + 1], c1);
            c2 = fmaf(w1[j + 2], h[j + 2], c2);
        }
        o3 = c0 + (c1 + c2);
        if (is_head)
            *reinterpret_cast<float4*>(orow + (T_ - 4)) = make_float4(o0, o1, o2, o3);
    }
}

extern "C" void kernel_launch(void* const* d_in, const int* in_sizes, int n_in,
                              void* d_out, int out_size)
{
    const float* x     = (const float*)d_in[0];
    const float* w_ih  = (const float*)d_in[1];
    const float* w_hh  = (const float*)d_in[2];
    const float* b_ih  = (const float*)d_in[3];
    const float* b_hh  = (const float*)d_in[4];
    const float* w_lin = (const float*)d_in[5];
    const float* b_lin = (const float*)d_in[6];
    float* out = (float*)d_out;
    rnn_kernel<<<GRID, THREADS>>>(x, w_ih, w_hh, b_ih, b_hh, w_lin, b_lin, out);
}